// round 13
// baseline (speedup 1.0000x reference)
#include <cuda_runtime.h>
#include <cstdint>

#define S_  128
#define E_  256
#define HD_ 512

// W stream: 256 superchunks (10240B) u = h*32+it.  it<16: [K|V], it>=16: [Q|R].
// slot = [n<64][kp<20], kp<16 valid: kk=kp>>3, q=kp&7 -> k=(it&15)*16+kk*8+(q>>1)+(q&1)*4.
__device__ __align__(16) float g_W[256 * 2560];

// smem floats: Xp[128][256] xor-swizzled @0 | Wc 3x2560 @32768 | Ks[128][72] @40448 | Vt[64][132] @49664
#define SMEM_BYTES 232448

__device__ __forceinline__ float f2tf(float x) {
    uint32_t u; asm("cvt.rna.tf32.f32 %0, %1;" : "=r"(u) : "f"(x)); return __uint_as_float(u);
}
__device__ __forceinline__ uint32_t fau(float x) { return __float_as_uint(x); }

__device__ __forceinline__ void mma8(float c[4],
                                     uint32_t a0, uint32_t a1, uint32_t a2, uint32_t a3,
                                     uint32_t b0, uint32_t b1) {
    asm volatile(
        "mma.sync.aligned.m16n8k8.row.col.f32.tf32.tf32.f32 "
        "{%0,%1,%2,%3},{%4,%5,%6,%7},{%8,%9},{%0,%1,%2,%3};"
        : "+f"(c[0]), "+f"(c[1]), "+f"(c[2]), "+f"(c[3])
        : "r"(a0), "r"(a1), "r"(a2), "r"(a3), "r"(b0), "r"(b1));
}
__device__ __forceinline__ void cpa16(void* smem_dst, const void* gsrc) {
    uint32_t s = (uint32_t)__cvta_generic_to_shared(smem_dst);
    asm volatile("cp.async.cg.shared.global [%0], [%1], 16;" :: "r"(s), "l"(gsrc));
}
__device__ __forceinline__ void issue_chunk(float* Wc, int buf, int u, int tid) {
    char* dst = (char*)Wc + buf * 10240;
    const char* src = (const char*)g_W + (size_t)u * 10240;
    for (int i = tid * 16; i < 10240; i += 4096) cpa16(dst + i, src + i);
    asm volatile("cp.async.commit_group;" ::: "memory");
}

// ---------------------------------------------------------------------------
// Prep: round W to tf32, pack superchunks (stride-20 slots).
// ---------------------------------------------------------------------------
__global__ void prep_kernel(const float* __restrict__ wq, const float* __restrict__ wk,
                            const float* __restrict__ wv, const float* __restrict__ wr) {
    const float* Ws[4] = {wq, wk, wv, wr};
    int idx = blockIdx.x * blockDim.x + threadIdx.x;
    if (idx >= 256 * 2560) return;
    int kp = idx % 20;
    int r1 = idx / 20;
    int n = r1 & 63;
    int r2 = r1 >> 6;
    int slot = r2 & 1;
    int u = r2 >> 1;
    int it = u & 31, h = u >> 5;
    float v = 0.0f;
    if (kp < 16) {
        int kk = kp >> 3, q = kp & 7;
        int k = (it & 15) * 16 + kk * 8 + (q >> 1) + (q & 1) * 4;
        int p = (it < 16) ? (slot ? 2 : 1) : (slot ? 3 : 0);
        v = f2tf(Ws[p][(size_t)k * HD_ + h * 64 + n]);
    }
    g_W[idx] = v;
}

// ---------------------------------------------------------------------------
// Fused MHA: one CTA per batch, 8 warps. 3-deep ring, distance-2, 1 sync/iter.
// ---------------------------------------------------------------------------
__global__ void __launch_bounds__(256, 1)
mha_kernel(const float* __restrict__ X, float* __restrict__ Out) {
    extern __shared__ float sm[];
    int b = blockIdx.x, tid = threadIdx.x;
    int w = tid >> 5, lane = tid & 31, g = lane >> 2, t = lane & 3;
    int kvslot = w >> 2;               // warps 0-3: K, warps 4-7: V
    int r0kv = (w & 3) * 32;
    int r0 = w * 16;

    float* Wc = sm + 32768;
    float* Ks = sm + 40448;
    float* Vt = sm + 49664;

    // prologue: chunks 0,1 -> bufs 0,1 (overlap with X staging)
    issue_chunk(Wc, 0, 0, tid);
    issue_chunk(Wc, 1, 1, tid);

    // Stage X -> Xp: tf32 round + k-pairing + xor-swizzle (stride 256).
    const float* Xg = X + (size_t)b * S_ * E_;
    for (int i = tid; i < S_ * E_ / 4; i += 256) {
        int r = i >> 6, c4 = (i & 63) * 4;
        float4 v = *(const float4*)&Xg[r * E_ + c4];
        float vv[4] = {v.x, v.y, v.z, v.w};
        int sw = (r & 7);
#pragma unroll
        for (int e = 0; e < 4; ++e) {
            int col = c4 + e, kt = col >> 3, q = col & 7;
            int pairpos = (q < 4) ? 2 * q : 2 * (q - 4) + 1;
            sm[r * 256 + (((kt ^ sw) << 3) + pairpos)] = f2tf(vv[e]);
        }
    }

    const float L2E = 1.4426950408889634f;
    int rb = 0, wb = 2;

    for (int h = 0; h < 8; ++h) {
        // ========== Phase 1: K (warps 0-3) & V (warps 4-7), Mt=2 ==========
        {
            float kv[2][8][4];
#pragma unroll
            for (int m = 0; m < 2; ++m)
#pragma unroll
                for (int j = 0; j < 8; ++j)
#pragma unroll
                    for (int i = 0; i < 4; ++i) kv[m][j][i] = 0.0f;

            for (int it = 0; it < 16; ++it) {
                int u = h * 32 + it;
                asm volatile("cp.async.wait_group 1;" ::: "memory");
                __syncthreads();
                if (u + 2 < 256) issue_chunk(Wc, wb, u + 2, tid);
                const float* Wb = Wc + rb * 2560 + kvslot * 1280;
#pragma unroll
                for (int kk = 0; kk < 2; ++kk) {
                    int s = it * 2 + kk;
                    int pc = ((s ^ g) << 3) + 2 * t;
                    float2 aA = *(const float2*)&sm[(r0kv + g) * 256 + pc];
                    float2 aB = *(const float2*)&sm[(r0kv + g + 8) * 256 + pc];
                    float2 aC = *(const float2*)&sm[(r0kv + g + 16) * 256 + pc];
                    float2 aD = *(const float2*)&sm[(r0kv + g + 24) * 256 + pc];
#pragma unroll
                    for (int j = 0; j < 8; ++j) {
                        float2 bb = *(const float2*)&Wb[(j * 8 + g) * 20 + kk * 8 + 2 * t];
                        uint32_t b0 = fau(bb.x), b1 = fau(bb.y);
                        mma8(kv[0][j], fau(aA.x), fau(aB.x), fau(aA.y), fau(aB.y), b0, b1);
                        mma8(kv[1][j], fau(aC.x), fau(aD.x), fau(aC.y), fau(aD.y), b0, b1);
                    }
                }
                rb = (rb == 2) ? 0 : rb + 1;
                wb = (wb == 2) ? 0 : wb + 1;
            }
            if (kvslot == 0) {
#pragma unroll
                for (int m = 0; m < 2; ++m)
#pragma unroll
                    for (int j = 0; j < 8; ++j) {
                        *(float2*)&Ks[(r0kv + 16 * m + g) * 72 + j * 8 + 2 * t] =
                            make_float2(f2tf(kv[m][j][0]), f2tf(kv[m][j][1]));
                        *(float2*)&Ks[(r0kv + 16 * m + g + 8) * 72 + j * 8 + 2 * t] =
                            make_float2(f2tf(kv[m][j][2]), f2tf(kv[m][j][3]));
                    }
            } else {
#pragma unroll
                for (int m = 0; m < 2; ++m)
#pragma unroll
                    for (int j = 0; j < 8; ++j) {
                        Vt[(j * 8 + 2 * t) * 132 + r0kv + 16 * m + g]         = f2tf(kv[m][j][0]);
                        Vt[(j * 8 + 2 * t + 1) * 132 + r0kv + 16 * m + g]     = f2tf(kv[m][j][1]);
                        Vt[(j * 8 + 2 * t) * 132 + r0kv + 16 * m + g + 8]     = f2tf(kv[m][j][2]);
                        Vt[(j * 8 + 2 * t + 1) * 132 + r0kv + 16 * m + g + 8] = f2tf(kv[m][j][3]);
                    }
            }
        }

        // ========== Phase 2: Q+R merged (per-warp 16 rows) ==========
        float qf[8][4], rf[8][4];
#pragma unroll
        for (int j = 0; j < 8; ++j)
#pragma unroll
            for (int i = 0; i < 4; ++i) { qf[j][i] = 0.0f; rf[j][i] = 0.0f; }

        for (int it = 16; it < 32; ++it) {
            int u = h * 32 + it;
            asm volatile("cp.async.wait_group 1;" ::: "memory");
            __syncthreads();
            if (u + 2 < 256) issue_chunk(Wc, wb, u + 2, tid);
            const float* Wb = Wc + rb * 2560;
#pragma unroll
            for (int kk = 0; kk < 2; ++kk) {
                int s = (it - 16) * 2 + kk;
                int pc = ((s ^ g) << 3) + 2 * t;
                float2 alo = *(const float2*)&sm[(r0 + g) * 256 + pc];
                float2 ahi = *(const float2*)&sm[(r0 + g + 8) * 256 + pc];
                uint32_t a0 = fau(alo.x), a1 = fau(ahi.x), a2 = fau(alo.y), a3 = fau(ahi.y);
#pragma unroll
                for (int j = 0; j < 8; ++j) {
                    float2 bq = *(const float2*)&Wb[(j * 8 + g) * 20 + kk * 8 + 2 * t];
                    mma8(qf[j], a0, a1, a2, a3, fau(bq.x), fau(bq.y));
                    float2 br = *(const float2*)&Wb[1280 + (j * 8 + g) * 20 + kk * 8 + 2 * t];
                    mma8(rf[j], a0, a1, a2, a3, fau(br.x), fau(br.y));
                }
            }
            rb = (rb == 2) ? 0 : rb + 1;
            wb = (wb == 2) ? 0 : wb + 1;
        }

        // round Q to tf32
#pragma unroll
        for (int j = 0; j < 8; ++j)
#pragma unroll
            for (int i = 0; i < 4; ++i) qf[j][i] = f2tf(qf[j][i]);

        // ---- scores = Q @ K^T (Q C-frags reused as A via k-order permutation) ----
        // Ks/Vt ordering: published by the phase-2 in-loop barriers.
        float s[16][4];
#pragma unroll
        for (int n = 0; n < 16; ++n)
#pragma unroll
            for (int i = 0; i < 4; ++i) s[n][i] = 0.0f;
#pragma unroll
        for (int jq = 0; jq < 8; ++jq) {
            uint32_t a0 = fau(qf[jq][0]);
            uint32_t a1 = fau(qf[jq][2]);
            uint32_t a2 = fau(qf[jq][1]);
            uint32_t a3 = fau(qf[jq][3]);
#pragma unroll
            for (int n = 0; n < 16; ++n) {
                float2 bb = *(const float2*)&Ks[(n * 8 + g) * 72 + jq * 8 + 2 * t];
                mma8(s[n], a0, a1, a2, a3, fau(bb.x), fau(bb.y));
            }
        }

        // ---- softmax (rows r0+g / r0+g+8) ----
        float m0 = -1e30f, m1 = -1e30f;
#pragma unroll
        for (int n = 0; n < 16; ++n) {
            m0 = fmaxf(m0, fmaxf(s[n][0], s[n][1]));
            m1 = fmaxf(m1, fmaxf(s[n][2], s[n][3]));
        }
        m0 = fmaxf(m0, __shfl_xor_sync(0xffffffffu, m0, 1));
        m0 = fmaxf(m0, __shfl_xor_sync(0xffffffffu, m0, 2));
        m1 = fmaxf(m1, __shfl_xor_sync(0xffffffffu, m1, 1));
        m1 = fmaxf(m1, __shfl_xor_sync(0xffffffffu, m1, 2));

        float sum0 = 0.0f, sum1 = 0.0f;
#pragma unroll
        for (int n = 0; n < 16; ++n) {
            float p0 = exp2f((s[n][0] - m0) * L2E);
            float p1 = exp2f((s[n][1] - m0) * L2E);
            float p2 = exp2f((s[n][2] - m1) * L2E);
            float p3 = exp2f((s[n][3] - m1) * L2E);
            sum0 += p0 + p1;
            sum1 += p2 + p3;
            s[n][0] = f2tf(p0); s[n][1] = f2tf(p1);
            s[n][2] = f2tf(p2); s[n][3] = f2tf(p3);
        }
        sum0 += __shfl_xor_sync(0xffffffffu, sum0, 1);
        sum0 += __shfl_xor_sync(0xffffffffu, sum0, 2);
        sum1 += __shfl_xor_sync(0xffffffffu, sum1, 1);
        sum1 += __shfl_xor_sync(0xffffffffu, sum1, 2);
        float sc0 = 1.0f / sum0, sc1 = 1.0f / sum1;

        // ---- O = P @ V ----
        float o[8][4];
#pragma unroll
        for (int j = 0; j < 8; ++j)
#pragma unroll
            for (int i = 0; i < 4; ++i) o[j][i] = 0.0f;
#pragma unroll
        for (int js = 0; js < 16; ++js) {
            uint32_t a0 = fau(s[js][0]);
            uint32_t a1 = fau(s[js][2]);
            uint32_t a2 = fau(s[js][1]);
            uint32_t a3 = fau(s[js][3]);
#pragma unroll
            for (int j = 0; j < 8; ++j) {
                float2 bb = *(const float2*)&Vt[(j * 8 + g) * 132 + js * 8 + 2 * t];
                mma8(o[j], a0, a1, a2, a3, fau(bb.x), fau(bb.y));
            }
        }

        // ---- epilogue: out = relu(O/rowsum + R) ----
        size_t ob = (size_t)b * S_ * HD_ + (size_t)h * 64;
#pragma unroll
        for (int j = 0; j < 8; ++j) {
            float2 lo, hi;
            lo.x = fmaxf(o[j][0] * sc0 + rf[j][0], 0.0f);
            lo.y = fmaxf(o[j][1] * sc0 + rf[j][1], 0.0f);
            hi.x = fmaxf(o[j][2] * sc1 + rf[j][2], 0.0f);
            hi.y = fmaxf(o[j][3] * sc1 + rf[j][3], 0.0f);
            *(float2*)&Out[ob + (size_t)(r0 + g) * HD_ + j * 8 + 2 * t] = lo;
            *(float2*)&Out[ob + (size_t)(r0 + g + 8) * HD_ + j * 8 + 2 * t] = hi;
        }
        // No end-of-head barrier: next head's phase-1 in-loop barriers order
        // the Ks/Vt overwrite (first scatter is after 16 synced iterations).
    }
}

extern "C" void kernel_launch(void* const* d_in, const int* in_sizes, int n_in,
                              void* d_out, int out_size) {
    const float* x  = (const float*)d_in[0];
    const float* wq = (const float*)d_in[1];
    const float* wk = (const float*)d_in[2];
    const float* wv = (const float*)d_in[3];
    const float* wr = (const float*)d_in[4];
    float* out = (float*)d_out;

    cudaFuncSetAttribute(mha_kernel, cudaFuncAttributeMaxDynamicSharedMemorySize, SMEM_BYTES);
    prep_kernel<<<2560, 256>>>(wq, wk, wv, wr);
    mha_kernel<<<1024, 256, SMEM_BYTES>>>(x, out);
}

// round 15
// speedup vs baseline: 1.2675x; 1.2675x over previous
#include <cuda_runtime.h>
#include <cstdint>

#define S_  128
#define E_  256
#define HD_ 512

// W stream: 256 superchunks x 3072 floats (12288 B each).
// Superchunk u = h*32+it: it<16 -> [K chunk16][V chunk16]; it>=16 -> [Q chunk16][R chunk16].
// Each slot: [n<64][kp<24]; kp<16: kk=kp>>3,q=kp&7 -> k = base16 + kk*8 + (q>>1) + (q&1)*4.
__device__ __align__(16) float g_W[256 * 3072];

#define SM_XP 0
#define SM_W  135168
#define SM_KS 159744
#define SM_VT 196608
#define SMEM_BYTES 231424

__device__ __forceinline__ float f2tf(float x) {
    uint32_t u; asm("cvt.rna.tf32.f32 %0, %1;" : "=r"(u) : "f"(x)); return __uint_as_float(u);
}
__device__ __forceinline__ uint32_t fau(float x) { return __float_as_uint(x); }

__device__ __forceinline__ void mma8(float c[4],
                                     uint32_t a0, uint32_t a1, uint32_t a2, uint32_t a3,
                                     uint32_t b0, uint32_t b1) {
    asm volatile(
        "mma.sync.aligned.m16n8k8.row.col.f32.tf32.tf32.f32 "
        "{%0,%1,%2,%3},{%4,%5,%6,%7},{%8,%9},{%0,%1,%2,%3};"
        : "+f"(c[0]), "+f"(c[1]), "+f"(c[2]), "+f"(c[3])
        : "r"(a0), "r"(a1), "r"(a2), "r"(a3), "r"(b0), "r"(b1));
}
__device__ __forceinline__ void cpa16(void* smem_dst, const void* gsrc) {
    uint32_t s = (uint32_t)__cvta_generic_to_shared(smem_dst);
    asm volatile("cp.async.cg.shared.global [%0], [%1], 16;" :: "r"(s), "l"(gsrc));
}

// ---------------------------------------------------------------------------
// Prep: round W to tf32 and pack the 256-superchunk stream (identical to R9).
// ---------------------------------------------------------------------------
__global__ void prep_kernel(const float* __restrict__ wq, const float* __restrict__ wk,
                            const float* __restrict__ wv, const float* __restrict__ wr) {
    const float* Ws[4] = {wq, wk, wv, wr};
    int idx = blockIdx.x * blockDim.x + threadIdx.x;
    if (idx >= 256 * 3072) return;
    int kp   = idx % 24;
    int n    = (idx / 24) & 63;
    int slot = (idx / (24 * 64)) & 1;
    int it   = (idx / (24 * 64 * 2)) & 31;
    int h    = idx / (24 * 64 * 2 * 32);
    float v = 0.0f;
    if (kp < 16) {
        int kk = kp >> 3, q = kp & 7;
        int k = (it & 15) * 16 + kk * 8 + (q >> 1) + (q & 1) * 4;
        int p = (it < 16) ? (slot ? 2 : 1) : (slot ? 3 : 0);
        v = f2tf(Ws[p][(size_t)k * HD_ + h * 64 + n]);
    }
    g_W[idx] = v;
}

// ---------------------------------------------------------------------------
// Fused MHA: one CTA per batch, 8 warps. R9 structure, single sync per iter.
// ---------------------------------------------------------------------------
__global__ void __launch_bounds__(256, 1)
mha_kernel(const float* __restrict__ X, float* __restrict__ Out) {
    extern __shared__ float sm[];
    int b = blockIdx.x, tid = threadIdx.x;
    int w = tid >> 5, lane = tid & 31, g = lane >> 2, t = lane & 3;

    // Stage X -> Xp (tf32 round + k-pairing, stride 264) — identical to R9.
    const float* Xg = X + (size_t)b * S_ * E_;
    for (int i = tid; i < S_ * E_ / 4; i += 256) {
        int r = i >> 6, c4 = (i & 63) * 4;
        float4 v = *(const float4*)&Xg[r * E_ + c4];
        float vv[4] = {v.x, v.y, v.z, v.w};
#pragma unroll
        for (int e = 0; e < 4; ++e) {
            int col = c4 + e, kt = col >> 3, q = col & 7;
            int kp = kt * 8 + ((q < 4) ? 2 * q : 2 * (q - 4) + 1);
            sm[r * 264 + kp] = f2tf(vv[e]);
        }
    }

    float* Wc = sm + SM_W / 4;
    float* Ks = sm + SM_KS / 4;
    float* Vt = sm + SM_VT / 4;

    // prologue: prefetch superchunk 0 into buf 0
    {
        const char* src = (const char*)g_W;
#pragma unroll
        for (int rep = 0; rep < 3; ++rep)
            cpa16((char*)Wc + tid * 16 + rep * 4096, src + tid * 16 + rep * 4096);
        asm volatile("cp.async.commit_group;" ::: "memory");
    }

    const float L2E = 1.4426950408889634f;

    for (int h = 0; h < 8; ++h) {
        float qf[8][4], rf[8][4];
#pragma unroll
        for (int j = 0; j < 8; ++j)
#pragma unroll
            for (int i = 0; i < 4; ++i) { qf[j][i] = 0.0f; rf[j][i] = 0.0f; }

        // ================= Phase 1: K (warps 0-3) & V (warps 4-7), 32-row tiles =================
        {
            float kv[2][8][4];
#pragma unroll
            for (int mi = 0; mi < 2; ++mi)
#pragma unroll
                for (int j = 0; j < 8; ++j)
#pragma unroll
                    for (int i = 0; i < 4; ++i) kv[mi][j][i] = 0.0f;

            int r0 = (w & 3) * 32;
            for (int it = 0; it < 16; ++it) {
                int u = h * 32 + it;
                asm volatile("cp.async.wait_group 0;" ::: "memory");  // chunk u landed (mine)
                __syncthreads();                                      // all visible; compute(u-1) done CTA-wide
                if (u + 1 < 256) {
                    const char* src = (const char*)g_W + (size_t)(u + 1) * 12288;
                    char* dst = (char*)Wc + ((u + 1) & 1) * 12288;
#pragma unroll
                    for (int rep = 0; rep < 3; ++rep)
                        cpa16(dst + tid * 16 + rep * 4096, src + tid * 16 + rep * 4096);
                    asm volatile("cp.async.commit_group;" ::: "memory");
                }
                const float* Wb = Wc + (u & 1) * 3072 + (w >= 4 ? 1536 : 0);
#pragma unroll
                for (int kk = 0; kk < 2; ++kk) {
                    int col = (it * 2 + kk) * 8 + 2 * t;
                    float2 aA = *(const float2*)&sm[(r0 + g) * 264 + col];
                    float2 aB = *(const float2*)&sm[(r0 + g + 8) * 264 + col];
                    float2 aC = *(const float2*)&sm[(r0 + g + 16) * 264 + col];
                    float2 aD = *(const float2*)&sm[(r0 + g + 24) * 264 + col];
#pragma unroll
                    for (int j = 0; j < 8; ++j) {
                        float2 bb = *(const float2*)&Wb[(j * 8 + g) * 24 + kk * 8 + 2 * t];
                        uint32_t b0 = fau(bb.x), b1 = fau(bb.y);
                        mma8(kv[0][j], fau(aA.x), fau(aB.x), fau(aA.y), fau(aB.y), b0, b1);
                        mma8(kv[1][j], fau(aC.x), fau(aD.x), fau(aC.y), fau(aD.y), b0, b1);
                    }
                }
            }
            if (w < 4) {
#pragma unroll
                for (int mi = 0; mi < 2; ++mi)
#pragma unroll
                    for (int j = 0; j < 8; ++j) {
                        *(float2*)&Ks[(r0 + 16 * mi + g) * 72 + j * 8 + 2 * t] =
                            make_float2(f2tf(kv[mi][j][0]), f2tf(kv[mi][j][1]));
                        *(float2*)&Ks[(r0 + 16 * mi + g + 8) * 72 + j * 8 + 2 * t] =
                            make_float2(f2tf(kv[mi][j][2]), f2tf(kv[mi][j][3]));
                    }
            } else {
#pragma unroll
                for (int mi = 0; mi < 2; ++mi)
#pragma unroll
                    for (int j = 0; j < 8; ++j) {
                        Vt[(j * 8 + 2 * t) * 136 + r0 + 16 * mi + g]         = f2tf(kv[mi][j][0]);
                        Vt[(j * 8 + 2 * t + 1) * 136 + r0 + 16 * mi + g]     = f2tf(kv[mi][j][1]);
                        Vt[(j * 8 + 2 * t) * 136 + r0 + 16 * mi + g + 8]     = f2tf(kv[mi][j][2]);
                        Vt[(j * 8 + 2 * t + 1) * 136 + r0 + 16 * mi + g + 8] = f2tf(kv[mi][j][3]);
                    }
            }
        }

        // ================= Phase 2: Q+R merged (all warps, 16-row tiles, n=128) =================
        int r0 = w * 16;
        for (int it = 16; it < 32; ++it) {
            int u = h * 32 + it;
            asm volatile("cp.async.wait_group 0;" ::: "memory");
            __syncthreads();
            if (u + 1 < 256) {
                const char* src = (const char*)g_W + (size_t)(u + 1) * 12288;
                char* dst = (char*)Wc + ((u + 1) & 1) * 12288;
#pragma unroll
                for (int rep = 0; rep < 3; ++rep)
                    cpa16(dst + tid * 16 + rep * 4096, src + tid * 16 + rep * 4096);
                asm volatile("cp.async.commit_group;" ::: "memory");
            }
            const float* Wb = Wc + (u & 1) * 3072;
#pragma unroll
            for (int kk = 0; kk < 2; ++kk) {
                int col = ((it - 16) * 2 + kk) * 8 + 2 * t;
                float2 alo = *(const float2*)&sm[(r0 + g) * 264 + col];
                float2 ahi = *(const float2*)&sm[(r0 + g + 8) * 264 + col];
                uint32_t a0 = fau(alo.x), a1 = fau(ahi.x), a2 = fau(alo.y), a3 = fau(ahi.y);
#pragma unroll
                for (int j = 0; j < 8; ++j) {
                    float2 bq = *(const float2*)&Wb[(j * 8 + g) * 24 + kk * 8 + 2 * t];
                    mma8(qf[j], a0, a1, a2, a3, fau(bq.x), fau(bq.y));
                    float2 br = *(const float2*)&Wb[1536 + (j * 8 + g) * 24 + kk * 8 + 2 * t];
                    mma8(rf[j], a0, a1, a2, a3, fau(br.x), fau(br.y));
                }
            }
        }

        // round Q to tf32
#pragma unroll
        for (int j = 0; j < 8; ++j)
#pragma unroll
            for (int i = 0; i < 4; ++i) qf[j][i] = f2tf(qf[j][i]);

        // ---- scores = Q @ K^T (Q C-frags reused as A via k-order permutation) ----
        // Ks/Vt writes ordered before these reads by phase-2's in-loop barriers.
        float s[16][4];
#pragma unroll
        for (int n = 0; n < 16; ++n)
#pragma unroll
            for (int i = 0; i < 4; ++i) s[n][i] = 0.0f;
#pragma unroll
        for (int jq = 0; jq < 8; ++jq) {
            uint32_t a0 = fau(qf[jq][0]);
            uint32_t a1 = fau(qf[jq][2]);
            uint32_t a2 = fau(qf[jq][1]);
            uint32_t a3 = fau(qf[jq][3]);
#pragma unroll
            for (int n = 0; n < 16; ++n) {
                float2 bb = *(const float2*)&Ks[(n * 8 + g) * 72 + jq * 8 + 2 * t];
                mma8(s[n], a0, a1, a2, a3, fau(bb.x), fau(bb.y));
            }
        }

        // ---- softmax (rows r0+g / r0+g+8) ----
        float m0 = -1e30f, m1 = -1e30f;
#pragma unroll
        for (int n = 0; n < 16; ++n) {
            m0 = fmaxf(m0, fmaxf(s[n][0], s[n][1]));
            m1 = fmaxf(m1, fmaxf(s[n][2], s[n][3]));
        }
        m0 = fmaxf(m0, __shfl_xor_sync(0xffffffffu, m0, 1));
        m0 = fmaxf(m0, __shfl_xor_sync(0xffffffffu, m0, 2));
        m1 = fmaxf(m1, __shfl_xor_sync(0xffffffffu, m1, 1));
        m1 = fmaxf(m1, __shfl_xor_sync(0xffffffffu, m1, 2));

        float sum0 = 0.0f, sum1 = 0.0f;
#pragma unroll
        for (int n = 0; n < 16; ++n) {
            float p0 = exp2f((s[n][0] - m0) * L2E);
            float p1 = exp2f((s[n][1] - m0) * L2E);
            float p2 = exp2f((s[n][2] - m1) * L2E);
            float p3 = exp2f((s[n][3] - m1) * L2E);
            sum0 += p0 + p1;
            sum1 += p2 + p3;
            s[n][0] = f2tf(p0); s[n][1] = f2tf(p1);
            s[n][2] = f2tf(p2); s[n][3] = f2tf(p3);
        }
        sum0 += __shfl_xor_sync(0xffffffffu, sum0, 1);
        sum0 += __shfl_xor_sync(0xffffffffu, sum0, 2);
        sum1 += __shfl_xor_sync(0xffffffffu, sum1, 1);
        sum1 += __shfl_xor_sync(0xffffffffu, sum1, 2);
        float sc0 = 1.0f / sum0, sc1 = 1.0f / sum1;

        // ---- O = P @ V ----
        float o[8][4];
#pragma unroll
        for (int j = 0; j < 8; ++j)
#pragma unroll
            for (int i = 0; i < 4; ++i) o[j][i] = 0.0f;
#pragma unroll
        for (int js = 0; js < 16; ++js) {
            uint32_t a0 = fau(s[js][0]);
            uint32_t a1 = fau(s[js][2]);
            uint32_t a2 = fau(s[js][1]);
            uint32_t a3 = fau(s[js][3]);
#pragma unroll
            for (int j = 0; j < 8; ++j) {
                float2 bb = *(const float2*)&Vt[(j * 8 + g) * 136 + js * 8 + 2 * t];
                mma8(o[j], a0, a1, a2, a3, fau(bb.x), fau(bb.y));
            }
        }

        // ---- epilogue: out = relu(O/rowsum + R) ----
        size_t ob = (size_t)b * S_ * HD_ + (size_t)h * 64;
#pragma unroll
        for (int j = 0; j < 8; ++j) {
            float2 lo, hi;
            lo.x = fmaxf(o[j][0] * sc0 + rf[j][0], 0.0f);
            lo.y = fmaxf(o[j][1] * sc0 + rf[j][1], 0.0f);
            hi.x = fmaxf(o[j][2] * sc1 + rf[j][2], 0.0f);
            hi.y = fmaxf(o[j][3] * sc1 + rf[j][3], 0.0f);
            *(float2*)&Out[ob + (size_t)(r0 + g) * HD_ + j * 8 + 2 * t] = lo;
            *(float2*)&Out[ob + (size_t)(r0 + g + 8) * HD_ + j * 8 + 2 * t] = hi;
        }
        // No end-of-head barrier: next head's phase-1 in-loop barriers order the
        // Ks/Vt overwrite (scatter happens only after 16 synced iterations).
    }
}

extern "C" void kernel_launch(void* const* d_in, const int* in_sizes, int n_in,
                              void* d_out, int out_size) {
    const float* x  = (const float*)d_in[0];
    const float* wq = (const float*)d_in[1];
    const float* wk = (const float*)d_in[2];
    const float* wv = (const float*)d_in[3];
    const float* wr = (const float*)d_in[4];
    float* out = (float*)d_out;

    cudaFuncSetAttribute(mha_kernel, cudaFuncAttributeMaxDynamicSharedMemorySize, SMEM_BYTES);
    prep_kernel<<<3072, 256>>>(wq, wk, wv, wr);
    mha_kernel<<<1024, 256, SMEM_BYTES>>>(x, out);
}